// round 16
// baseline (speedup 1.0000x reference)
#include <cuda_runtime.h>
#include <cuda_fp16.h>

#define NN 100000
#define NE 3200000
#define HD 64
#define CAP 96                      // per-node bucket capacity (multiple of 8)

// ---- scratch (__device__ globals; no allocation allowed) ----
// g_hw MUST be 128B-aligned: each node row is 128 B; alignment makes every
// row exactly one L1 line -> 4 wavefronts per gather LDG.128 instead of 8.
__device__ __align__(16)  int    g_cnt[NN];             // in-degree -> padded degree
__device__ __align__(128) int    g_bucket[NN * CAP];    // per-dst src lists (sentinel=NN)
__device__ __align__(16)  float  g_dis[NN];             // (1+deg)^{-1/2}
__device__ __align__(128) float  g_h [NN * HD];         // activations (fp32)
__device__ __align__(128) __half g_hw[(NN + 1) * HD];   // dis*(h@W) fp16; row NN = zeros
__device__ __align__(16)  float  g_hw3[NN + 1];         // layer-3 column; [NN] = 0

static __device__ __forceinline__ __half2 u2h(unsigned u) {
    return *reinterpret_cast<__half2*>(&u);
}

// ================= graph preprocessing =================
__global__ void k_init() {
    int i = blockIdx.x * blockDim.x + threadIdx.x;
    if (i >= NN) return;
    g_cnt[i] = 0;
    if (i < HD) g_hw[NN * HD + i] = __float2half(0.f);   // zero sentinel row
    if (i == 0) g_hw3[NN] = 0.f;
}

// single pass: bucket fill (4 edges per thread via int4)
__global__ void k_fill(const int* __restrict__ ei) {
    int t = blockIdx.x * blockDim.x + threadIdx.x;
    if (t >= NE / 4) return;
    int4 s = reinterpret_cast<const int4*>(ei)[t];
    int4 d = reinterpret_cast<const int4*>(ei + NE)[t];
    int p;
    p = atomicAdd(&g_cnt[d.x], 1); if (p < CAP) g_bucket[d.x * CAP + p] = s.x;
    p = atomicAdd(&g_cnt[d.y], 1); if (p < CAP) g_bucket[d.y * CAP + p] = s.y;
    p = atomicAdd(&g_cnt[d.z], 1); if (p < CAP) g_bucket[d.z * CAP + p] = s.z;
    p = atomicAdd(&g_cnt[d.w], 1); if (p < CAP) g_bucket[d.w * CAP + p] = s.w;
}

// ================= dense transforms (dis pre-scaled, fp16 out) =================
// gemm1 with fused finish: dis / pad-to-8 / padded-count, then register-tiled GEMM
__global__ void __launch_bounds__(128) k_gemm1(const float* __restrict__ x,
                                               const float* __restrict__ W1) {
    __shared__ float sW[5][HD];           // 320 floats
    __shared__ float sx[128][5];
    int tid = threadIdx.x;                // 0..127
    int tx = tid & 7;
    int ty = tid >> 3;
    int node0 = blockIdx.x * 128;

    // ---- fused finish: one node per thread ----
    int mynode = node0 + tid;
    if (mynode < NN) {
        int d = g_cnt[mynode];
        if (d > CAP) d = CAP;
        g_dis[mynode] = rsqrtf(1.0f + (float)d);     // +1 self-loop
        int pd = (d + 7) & ~7;                        // pad to multiple of 8
        int o = mynode * CAP;
        for (int k = d; k < pd; k++) g_bucket[o + k] = NN;
        g_cnt[mynode] = pd;
    }

    // load W1: 320 floats with 128 threads = 128 + 128 + 64
    (&sW[0][0])[tid]       = W1[tid];
    (&sW[0][0])[tid + 128] = W1[tid + 128];
    if (tid < 64) (&sW[0][0])[tid + 256] = W1[tid + 256];
    int xbase = node0 * 5;
    #pragma unroll
    for (int i = 0; i < 5; i++) {
        int idx = tid + i * 128;
        int gi = xbase + idx;
        (&sx[0][0])[idx] = (gi < NN * 5) ? x[gi] : 0.f;
    }
    __syncthreads();

    float acc[8][8];
    #pragma unroll
    for (int i = 0; i < 8; i++)
        #pragma unroll
        for (int j = 0; j < 8; j++) acc[i][j] = 0.f;

    #pragma unroll
    for (int k = 0; k < 5; k++) {
        float4 w0 = *reinterpret_cast<const float4*>(&sW[k][tx * 8]);
        float4 w1 = *reinterpret_cast<const float4*>(&sW[k][tx * 8 + 4]);
        float a[8];
        #pragma unroll
        for (int i = 0; i < 8; i++) a[i] = sx[ty * 8 + i][k];
        #pragma unroll
        for (int i = 0; i < 8; i++) {
            acc[i][0] += a[i] * w0.x; acc[i][1] += a[i] * w0.y;
            acc[i][2] += a[i] * w0.z; acc[i][3] += a[i] * w0.w;
            acc[i][4] += a[i] * w1.x; acc[i][5] += a[i] * w1.y;
            acc[i][6] += a[i] * w1.z; acc[i][7] += a[i] * w1.w;
        }
    }

    #pragma unroll
    for (int i = 0; i < 8; i++) {
        int node = node0 + ty * 8 + i;
        if (node >= NN) break;
        float dn = g_dis[node];
        __half2 p0 = __floats2half2_rn(acc[i][0] * dn, acc[i][1] * dn);
        __half2 p1 = __floats2half2_rn(acc[i][2] * dn, acc[i][3] * dn);
        __half2 p2 = __floats2half2_rn(acc[i][4] * dn, acc[i][5] * dn);
        __half2 p3 = __floats2half2_rn(acc[i][6] * dn, acc[i][7] * dn);
        uint4 pk;
        pk.x = *reinterpret_cast<unsigned*>(&p0);
        pk.y = *reinterpret_cast<unsigned*>(&p1);
        pk.z = *reinterpret_cast<unsigned*>(&p2);
        pk.w = *reinterpret_cast<unsigned*>(&p3);
        *reinterpret_cast<uint4*>(g_hw + (size_t)node * HD + tx * 8) = pk;
    }
}

// register-tiled: 128 threads, 128 nodes x 64 cols per block, 8x8 per thread
__global__ void __launch_bounds__(128) k_gemm2(const float* __restrict__ W2) {
    __shared__ float sW[HD][HD];
    __shared__ float sh[128][HD + 1];
    int tid = threadIdx.x;
    int tx = tid & 7;
    int ty = tid >> 3;
    int node0 = blockIdx.x * 128;

    #pragma unroll
    for (int i = 0; i < 8; i++) {
        int idx = tid + i * 128;
        reinterpret_cast<float4*>(&sW[0][0])[idx] =
            reinterpret_cast<const float4*>(W2)[idx];
    }
    #pragma unroll
    for (int i = 0; i < 16; i++) {
        int fidx = tid + i * 128;
        int r = fidx >> 4, c4 = fidx & 15;
        int node = node0 + r;
        float4 v = (node < NN)
            ? reinterpret_cast<const float4*>(g_h + (size_t)node * HD)[c4]
            : make_float4(0.f, 0.f, 0.f, 0.f);
        sh[r][c4 * 4 + 0] = v.x; sh[r][c4 * 4 + 1] = v.y;
        sh[r][c4 * 4 + 2] = v.z; sh[r][c4 * 4 + 3] = v.w;
    }
    __syncthreads();

    float acc[8][8];
    #pragma unroll
    for (int i = 0; i < 8; i++)
        #pragma unroll
        for (int j = 0; j < 8; j++) acc[i][j] = 0.f;

    #pragma unroll 4
    for (int k = 0; k < HD; k++) {
        float4 w0 = *reinterpret_cast<const float4*>(&sW[k][tx * 8]);
        float4 w1 = *reinterpret_cast<const float4*>(&sW[k][tx * 8 + 4]);
        float a[8];
        #pragma unroll
        for (int i = 0; i < 8; i++) a[i] = sh[ty * 8 + i][k];
        #pragma unroll
        for (int i = 0; i < 8; i++) {
            acc[i][0] += a[i] * w0.x; acc[i][1] += a[i] * w0.y;
            acc[i][2] += a[i] * w0.z; acc[i][3] += a[i] * w0.w;
            acc[i][4] += a[i] * w1.x; acc[i][5] += a[i] * w1.y;
            acc[i][6] += a[i] * w1.z; acc[i][7] += a[i] * w1.w;
        }
    }

    #pragma unroll
    for (int i = 0; i < 8; i++) {
        int node = node0 + ty * 8 + i;
        if (node >= NN) break;
        float dn = g_dis[node];
        __half2 p0 = __floats2half2_rn(acc[i][0] * dn, acc[i][1] * dn);
        __half2 p1 = __floats2half2_rn(acc[i][2] * dn, acc[i][3] * dn);
        __half2 p2 = __floats2half2_rn(acc[i][4] * dn, acc[i][5] * dn);
        __half2 p3 = __floats2half2_rn(acc[i][6] * dn, acc[i][7] * dn);
        uint4 pk;
        pk.x = *reinterpret_cast<unsigned*>(&p0);
        pk.y = *reinterpret_cast<unsigned*>(&p1);
        pk.z = *reinterpret_cast<unsigned*>(&p2);
        pk.w = *reinterpret_cast<unsigned*>(&p3);
        *reinterpret_cast<uint4*>(g_hw + (size_t)node * HD + tx * 8) = pk;
    }
}

__global__ void k_gemm3(const float* __restrict__ W3) {
    __shared__ float sW[HD];
    int tid = threadIdx.x;
    if (tid < HD) sW[tid] = W3[tid];
    __syncthreads();
    int lane = tid & 31;
    int node = blockIdx.x * 8 + (tid >> 5);
    if (node >= NN) return;
    const float* row = g_h + (size_t)node * HD;
    float s = row[lane] * sW[lane] + row[lane + 32] * sW[lane + 32];
    #pragma unroll
    for (int off = 16; off > 0; off >>= 1)
        s += __shfl_down_sync(0xFFFFFFFFu, s, off);
    if (lane == 0) g_hw3[node] = s * g_dis[node];
}

// ================= gather (message passing) =================
// one warp per node; lane = (edge-slot lg 0..3, col-group lc 0..7).
// Software-pipelined idx loads + fully unrolled 8-edge pair steps (HADD2).
__global__ void k_gather64(const float* __restrict__ bias) {
    int lane = threadIdx.x & 31;
    int node = blockIdx.x * 8 + (threadIdx.x >> 5);
    if (node >= NN) return;
    int start = node * CAP;
    int pend  = start + g_cnt[node];   // padded degree (multiple of 8)
    int lg = lane >> 3;
    int lc = lane & 7;

    float acc[8];
    if (lg == 0) {                // self-loop row, counted once
        uint4 v = *reinterpret_cast<const uint4*>(g_hw + (size_t)node * HD + lc * 8);
        float2 f0 = __half22float2(u2h(v.x));
        float2 f1 = __half22float2(u2h(v.y));
        float2 f2 = __half22float2(u2h(v.z));
        float2 f3 = __half22float2(u2h(v.w));
        acc[0] = f0.x; acc[1] = f0.y; acc[2] = f1.x; acc[3] = f1.y;
        acc[4] = f2.x; acc[5] = f2.y; acc[6] = f3.x; acc[7] = f3.y;
    } else {
        #pragma unroll
        for (int k = 0; k < 8; k++) acc[k] = 0.f;
    }

    // software-pipelined batches: prefetch next batch's indices
    int base = start;
    int idx = (base + lane < pend) ? g_bucket[base + lane] : NN;
    while (base < pend) {
        int nbase = base + 32;
        int nidx = (nbase + lane < pend) ? g_bucket[nbase + lane] : NN;
        int m = pend - base; if (m > 32) m = 32;   // multiple of 8
        #pragma unroll 4
        for (int q = 0; q < m; q += 8) {
            int s0 = __shfl_sync(0xFFFFFFFFu, idx, q + lg);
            int s1 = __shfl_sync(0xFFFFFFFFu, idx, q + 4 + lg);
            uint4 v0 = *reinterpret_cast<const uint4*>(g_hw + (size_t)s0 * HD + lc * 8);
            uint4 v1 = *reinterpret_cast<const uint4*>(g_hw + (size_t)s1 * HD + lc * 8);
            __half2 h0 = __hadd2(u2h(v0.x), u2h(v1.x));
            __half2 h1 = __hadd2(u2h(v0.y), u2h(v1.y));
            __half2 h2 = __hadd2(u2h(v0.z), u2h(v1.z));
            __half2 h3 = __hadd2(u2h(v0.w), u2h(v1.w));
            float2 f0 = __half22float2(h0);
            float2 f1 = __half22float2(h1);
            float2 f2 = __half22float2(h2);
            float2 f3 = __half22float2(h3);
            acc[0] += f0.x; acc[1] += f0.y; acc[2] += f1.x; acc[3] += f1.y;
            acc[4] += f2.x; acc[5] += f2.y; acc[6] += f3.x; acc[7] += f3.y;
        }
        base = nbase;
        idx = nidx;
    }

    // fold the 4 edge-slot groups
    #pragma unroll
    for (int off = 8; off <= 16; off <<= 1) {
        #pragma unroll
        for (int k = 0; k < 8; k++)
            acc[k] += __shfl_xor_sync(0xFFFFFFFFu, acc[k], off);
    }

    if (lane < 8) {
        float dn = g_dis[node];
        float4 r0, r1;
        r0.x = fmaxf(fmaf(dn, acc[0], bias[lane * 8 + 0]), 0.f);
        r0.y = fmaxf(fmaf(dn, acc[1], bias[lane * 8 + 1]), 0.f);
        r0.z = fmaxf(fmaf(dn, acc[2], bias[lane * 8 + 2]), 0.f);
        r0.w = fmaxf(fmaf(dn, acc[3], bias[lane * 8 + 3]), 0.f);
        r1.x = fmaxf(fmaf(dn, acc[4], bias[lane * 8 + 4]), 0.f);
        r1.y = fmaxf(fmaf(dn, acc[5], bias[lane * 8 + 5]), 0.f);
        r1.z = fmaxf(fmaf(dn, acc[6], bias[lane * 8 + 6]), 0.f);
        r1.w = fmaxf(fmaf(dn, acc[7], bias[lane * 8 + 7]), 0.f);
        float* o = g_h + (size_t)node * HD + lane * 8;
        *reinterpret_cast<float4*>(o)     = r0;
        *reinterpret_cast<float4*>(o + 4) = r1;
    }
}

// layer 3: one warp per node, lanes stride edges (sentinel reads 0)
__global__ void k_gather1(float* __restrict__ out, const float* __restrict__ b3) {
    int lane = threadIdx.x & 31;
    int node = blockIdx.x * 8 + (threadIdx.x >> 5);
    if (node >= NN) return;
    int start = node * CAP;
    int end   = start + g_cnt[node];
    float acc = 0.f;
    int i = start + lane;
    int idx = (i < end) ? g_bucket[i] : NN;
    while (i < end) {
        int ni = i + 32;
        int nidx = (ni < end) ? g_bucket[ni] : NN;
        acc += g_hw3[idx];
        i = ni;
        idx = nidx;
    }
    #pragma unroll
    for (int off = 16; off > 0; off >>= 1)
        acc += __shfl_down_sync(0xFFFFFFFFu, acc, off);
    if (lane == 0)
        out[node] = g_dis[node] * (acc + g_hw3[node]) + b3[0];
}

// ================= launch =================
extern "C" void kernel_launch(void* const* d_in, const int* in_sizes, int n_in,
                              void* d_out, int out_size) {
    const float* x  = (const float*)d_in[0];
    const int*   ei = (const int*)d_in[1];
    const float* W1 = (const float*)d_in[2];
    const float* b1 = (const float*)d_in[3];
    const float* W2 = (const float*)d_in[4];
    const float* b2 = (const float*)d_in[5];
    const float* W3 = (const float*)d_in[6];
    const float* b3 = (const float*)d_in[7];
    float* out = (float*)d_out;

    const int TB = 256;
    k_init<<<(NN + TB - 1) / TB, TB>>>();
    k_fill<<<(NE / 4 + TB - 1) / TB, TB>>>(ei);

    // --- layer 1 (gemm1 also finalizes dis/padding) ---
    k_gemm1<<<(NN + 127) / 128, 128>>>(x, W1);
    k_gather64<<<(NN + 7) / 8, TB>>>(b1);       // launch index 3: profiled

    // --- layer 2 ---
    k_gemm2<<<(NN + 127) / 128, 128>>>(W2);
    k_gather64<<<(NN + 7) / 8, TB>>>(b2);

    // --- layer 3 ---
    k_gemm3<<<(NN + 7) / 8, TB>>>(W3);
    k_gather1<<<(NN + 7) / 8, TB>>>(out, b3);
}

// round 17
// speedup vs baseline: 1.0153x; 1.0153x over previous
#include <cuda_runtime.h>
#include <cuda_fp16.h>

#define NN 100000
#define NE 3200000
#define HD 64
#define CAP 96                      // per-node bucket capacity (multiple of 8)

// ---- scratch (__device__ globals; zero-initialized at module load) ----
// INVARIANT: g_cnt is all-zero at kernel_launch entry (zeroed by k_gather1 tail).
__device__ __align__(16)  int    g_cnt[NN];             // in-degree -> padded degree
__device__ __align__(128) int    g_bucket[NN * CAP];    // per-dst src lists (sentinel=NN)
__device__ __align__(16)  float  g_dis[NN];             // (1+deg)^{-1/2}
__device__ __align__(128) float  g_h [NN * HD];         // layer-1 activations (fp32)
__device__ __align__(128) __half g_hw[(NN + 1) * HD];   // dis*(h@W) fp16; row NN = zeros
__device__ __align__(16)  float  g_hw3[NN + 1];         // layer-3 column; [NN] = 0

static __device__ __forceinline__ __half2 u2h(unsigned u) {
    return *reinterpret_cast<__half2*>(&u);
}

// ================= graph preprocessing =================
// single pass: bucket fill (4 edges per thread via int4); g_cnt starts zeroed
__global__ void k_fill(const int* __restrict__ ei) {
    int t = blockIdx.x * blockDim.x + threadIdx.x;
    if (t >= NE / 4) return;
    int4 s = reinterpret_cast<const int4*>(ei)[t];
    int4 d = reinterpret_cast<const int4*>(ei + NE)[t];
    int p;
    p = atomicAdd(&g_cnt[d.x], 1); if (p < CAP) g_bucket[d.x * CAP + p] = s.x;
    p = atomicAdd(&g_cnt[d.y], 1); if (p < CAP) g_bucket[d.y * CAP + p] = s.y;
    p = atomicAdd(&g_cnt[d.z], 1); if (p < CAP) g_bucket[d.z * CAP + p] = s.z;
    p = atomicAdd(&g_cnt[d.w], 1); if (p < CAP) g_bucket[d.w * CAP + p] = s.w;
}

// ================= dense transforms (dis pre-scaled, fp16 out) =================
// gemm1 with fused finish: dis / pad-to-8 / padded-count / sentinel row
__global__ void __launch_bounds__(128) k_gemm1(const float* __restrict__ x,
                                               const float* __restrict__ W1) {
    __shared__ float sW[5][HD];           // 320 floats
    __shared__ float sx[128][5];
    int tid = threadIdx.x;                // 0..127
    int tx = tid & 7;
    int ty = tid >> 3;
    int node0 = blockIdx.x * 128;

    // ---- fused finish: one node per thread ----
    int mynode = node0 + tid;
    if (mynode < NN) {
        int d = g_cnt[mynode];
        if (d > CAP) d = CAP;
        g_dis[mynode] = rsqrtf(1.0f + (float)d);     // +1 self-loop
        int pd = (d + 7) & ~7;                        // pad to multiple of 8
        int o = mynode * CAP;
        for (int k = d; k < pd; k++) g_bucket[o + k] = NN;
        g_cnt[mynode] = pd;
    }
    if (blockIdx.x == 0 && tid < HD)
        g_hw[NN * HD + tid] = __float2half(0.f);      // zero sentinel row

    // load W1: 320 floats with 128 threads = 128 + 128 + 64
    (&sW[0][0])[tid]       = W1[tid];
    (&sW[0][0])[tid + 128] = W1[tid + 128];
    if (tid < 64) (&sW[0][0])[tid + 256] = W1[tid + 256];
    int xbase = node0 * 5;
    #pragma unroll
    for (int i = 0; i < 5; i++) {
        int idx = tid + i * 128;
        int gi = xbase + idx;
        (&sx[0][0])[idx] = (gi < NN * 5) ? x[gi] : 0.f;
    }
    __syncthreads();

    float acc[8][8];
    #pragma unroll
    for (int i = 0; i < 8; i++)
        #pragma unroll
        for (int j = 0; j < 8; j++) acc[i][j] = 0.f;

    #pragma unroll
    for (int k = 0; k < 5; k++) {
        float4 w0 = *reinterpret_cast<const float4*>(&sW[k][tx * 8]);
        float4 w1 = *reinterpret_cast<const float4*>(&sW[k][tx * 8 + 4]);
        float a[8];
        #pragma unroll
        for (int i = 0; i < 8; i++) a[i] = sx[ty * 8 + i][k];
        #pragma unroll
        for (int i = 0; i < 8; i++) {
            acc[i][0] += a[i] * w0.x; acc[i][1] += a[i] * w0.y;
            acc[i][2] += a[i] * w0.z; acc[i][3] += a[i] * w0.w;
            acc[i][4] += a[i] * w1.x; acc[i][5] += a[i] * w1.y;
            acc[i][6] += a[i] * w1.z; acc[i][7] += a[i] * w1.w;
        }
    }

    #pragma unroll
    for (int i = 0; i < 8; i++) {
        int node = node0 + ty * 8 + i;
        if (node >= NN) break;
        float dn = g_dis[node];
        __half2 p0 = __floats2half2_rn(acc[i][0] * dn, acc[i][1] * dn);
        __half2 p1 = __floats2half2_rn(acc[i][2] * dn, acc[i][3] * dn);
        __half2 p2 = __floats2half2_rn(acc[i][4] * dn, acc[i][5] * dn);
        __half2 p3 = __floats2half2_rn(acc[i][6] * dn, acc[i][7] * dn);
        uint4 pk;
        pk.x = *reinterpret_cast<unsigned*>(&p0);
        pk.y = *reinterpret_cast<unsigned*>(&p1);
        pk.z = *reinterpret_cast<unsigned*>(&p2);
        pk.w = *reinterpret_cast<unsigned*>(&p3);
        *reinterpret_cast<uint4*>(g_hw + (size_t)node * HD + tx * 8) = pk;
    }
}

// register-tiled: 128 threads, 128 nodes x 64 cols per block, 8x8 per thread
__global__ void __launch_bounds__(128) k_gemm2(const float* __restrict__ W2) {
    __shared__ float sW[HD][HD];
    __shared__ float sh[128][HD + 1];
    int tid = threadIdx.x;
    int tx = tid & 7;
    int ty = tid >> 3;
    int node0 = blockIdx.x * 128;

    #pragma unroll
    for (int i = 0; i < 8; i++) {
        int idx = tid + i * 128;
        reinterpret_cast<float4*>(&sW[0][0])[idx] =
            reinterpret_cast<const float4*>(W2)[idx];
    }
    #pragma unroll
    for (int i = 0; i < 16; i++) {
        int fidx = tid + i * 128;
        int r = fidx >> 4, c4 = fidx & 15;
        int node = node0 + r;
        float4 v = (node < NN)
            ? reinterpret_cast<const float4*>(g_h + (size_t)node * HD)[c4]
            : make_float4(0.f, 0.f, 0.f, 0.f);
        sh[r][c4 * 4 + 0] = v.x; sh[r][c4 * 4 + 1] = v.y;
        sh[r][c4 * 4 + 2] = v.z; sh[r][c4 * 4 + 3] = v.w;
    }
    __syncthreads();

    float acc[8][8];
    #pragma unroll
    for (int i = 0; i < 8; i++)
        #pragma unroll
        for (int j = 0; j < 8; j++) acc[i][j] = 0.f;

    #pragma unroll 4
    for (int k = 0; k < HD; k++) {
        float4 w0 = *reinterpret_cast<const float4*>(&sW[k][tx * 8]);
        float4 w1 = *reinterpret_cast<const float4*>(&sW[k][tx * 8 + 4]);
        float a[8];
        #pragma unroll
        for (int i = 0; i < 8; i++) a[i] = sh[ty * 8 + i][k];
        #pragma unroll
        for (int i = 0; i < 8; i++) {
            acc[i][0] += a[i] * w0.x; acc[i][1] += a[i] * w0.y;
            acc[i][2] += a[i] * w0.z; acc[i][3] += a[i] * w0.w;
            acc[i][4] += a[i] * w1.x; acc[i][5] += a[i] * w1.y;
            acc[i][6] += a[i] * w1.z; acc[i][7] += a[i] * w1.w;
        }
    }

    #pragma unroll
    for (int i = 0; i < 8; i++) {
        int node = node0 + ty * 8 + i;
        if (node >= NN) break;
        float dn = g_dis[node];
        __half2 p0 = __floats2half2_rn(acc[i][0] * dn, acc[i][1] * dn);
        __half2 p1 = __floats2half2_rn(acc[i][2] * dn, acc[i][3] * dn);
        __half2 p2 = __floats2half2_rn(acc[i][4] * dn, acc[i][5] * dn);
        __half2 p3 = __floats2half2_rn(acc[i][6] * dn, acc[i][7] * dn);
        uint4 pk;
        pk.x = *reinterpret_cast<unsigned*>(&p0);
        pk.y = *reinterpret_cast<unsigned*>(&p1);
        pk.z = *reinterpret_cast<unsigned*>(&p2);
        pk.w = *reinterpret_cast<unsigned*>(&p3);
        *reinterpret_cast<uint4*>(g_hw + (size_t)node * HD + tx * 8) = pk;
    }
}

// ================= gather (message passing) =================
// one warp per node; lane = (edge-slot lg 0..3, col-group lc 0..7).
// FUSE_W3=false: writes relu activation to g_h (layer 1).
// FUSE_W3=true:  computes hw3 = dis * dot(relu_act, W3) directly (layer 2),
//                skipping the g_h store and the separate gemm3 kernel.
template <bool FUSE_W3>
__global__ void k_gather64(const float* __restrict__ bias,
                           const float* __restrict__ W3) {
    int lane = threadIdx.x & 31;
    int node = blockIdx.x * 8 + (threadIdx.x >> 5);
    if (FUSE_W3 && blockIdx.x == 0 && threadIdx.x == 0)
        g_hw3[NN] = 0.f;                                // sentinel for gather1
    if (node >= NN) return;
    int start = node * CAP;
    int pend  = start + g_cnt[node];   // padded degree (multiple of 8)
    int lg = lane >> 3;
    int lc = lane & 7;

    float acc[8];
    if (lg == 0) {                // self-loop row, counted once
        uint4 v = *reinterpret_cast<const uint4*>(g_hw + (size_t)node * HD + lc * 8);
        float2 f0 = __half22float2(u2h(v.x));
        float2 f1 = __half22float2(u2h(v.y));
        float2 f2 = __half22float2(u2h(v.z));
        float2 f3 = __half22float2(u2h(v.w));
        acc[0] = f0.x; acc[1] = f0.y; acc[2] = f1.x; acc[3] = f1.y;
        acc[4] = f2.x; acc[5] = f2.y; acc[6] = f3.x; acc[7] = f3.y;
    } else {
        #pragma unroll
        for (int k = 0; k < 8; k++) acc[k] = 0.f;
    }

    // software-pipelined batches: prefetch next batch's indices
    int base = start;
    int idx = (base + lane < pend) ? g_bucket[base + lane] : NN;
    while (base < pend) {
        int nbase = base + 32;
        int nidx = (nbase + lane < pend) ? g_bucket[nbase + lane] : NN;
        int m = pend - base; if (m > 32) m = 32;   // multiple of 8
        #pragma unroll 4
        for (int q = 0; q < m; q += 8) {
            int s0 = __shfl_sync(0xFFFFFFFFu, idx, q + lg);
            int s1 = __shfl_sync(0xFFFFFFFFu, idx, q + 4 + lg);
            uint4 v0 = *reinterpret_cast<const uint4*>(g_hw + (size_t)s0 * HD + lc * 8);
            uint4 v1 = *reinterpret_cast<const uint4*>(g_hw + (size_t)s1 * HD + lc * 8);
            __half2 h0 = __hadd2(u2h(v0.x), u2h(v1.x));
            __half2 h1 = __hadd2(u2h(v0.y), u2h(v1.y));
            __half2 h2 = __hadd2(u2h(v0.z), u2h(v1.z));
            __half2 h3 = __hadd2(u2h(v0.w), u2h(v1.w));
            float2 f0 = __half22float2(h0);
            float2 f1 = __half22float2(h1);
            float2 f2 = __half22float2(h2);
            float2 f3 = __half22float2(h3);
            acc[0] += f0.x; acc[1] += f0.y; acc[2] += f1.x; acc[3] += f1.y;
            acc[4] += f2.x; acc[5] += f2.y; acc[6] += f3.x; acc[7] += f3.y;
        }
        base = nbase;
        idx = nidx;
    }

    // fold the 4 edge-slot groups
    #pragma unroll
    for (int off = 8; off <= 16; off <<= 1) {
        #pragma unroll
        for (int k = 0; k < 8; k++)
            acc[k] += __shfl_xor_sync(0xFFFFFFFFu, acc[k], off);
    }

    float dn = g_dis[node];
    float r[8];
    if (lane < 8) {
        #pragma unroll
        for (int k = 0; k < 8; k++)
            r[k] = fmaxf(fmaf(dn, acc[k], bias[lane * 8 + k]), 0.f);
    }

    if (FUSE_W3) {
        // hw3 = dn * dot(relu_act, W3); lanes 0-7 hold 8 cols each
        float part = 0.f;
        if (lane < 8) {
            float4 w0 = *reinterpret_cast<const float4*>(W3 + lane * 8);
            float4 w1 = *reinterpret_cast<const float4*>(W3 + lane * 8 + 4);
            part = r[0] * w0.x + r[1] * w0.y + r[2] * w0.z + r[3] * w0.w
                 + r[4] * w1.x + r[5] * w1.y + r[6] * w1.z + r[7] * w1.w;
        }
        #pragma unroll
        for (int off = 4; off > 0; off >>= 1)
            part += __shfl_xor_sync(0xFFFFFFFFu, part, off);
        if (lane == 0) g_hw3[node] = part * dn;
    } else {
        if (lane < 8) {
            float* o = g_h + (size_t)node * HD + lane * 8;
            *reinterpret_cast<float4*>(o)     = make_float4(r[0], r[1], r[2], r[3]);
            *reinterpret_cast<float4*>(o + 4) = make_float4(r[4], r[5], r[6], r[7]);
        }
    }
}

// layer 3: one warp per node; also resets g_cnt for the next graph replay
__global__ void k_gather1(float* __restrict__ out, const float* __restrict__ b3) {
    int lane = threadIdx.x & 31;
    int node = blockIdx.x * 8 + (threadIdx.x >> 5);
    if (node >= NN) return;
    int start = node * CAP;
    int end   = start + g_cnt[node];
    float acc = 0.f;
    int i = start + lane;
    int idx = (i < end) ? g_bucket[i] : NN;
    while (i < end) {
        int ni = i + 32;
        int nidx = (ni < end) ? g_bucket[ni] : NN;
        acc += g_hw3[idx];
        i = ni;
        idx = nidx;
    }
    #pragma unroll
    for (int off = 16; off > 0; off >>= 1)
        acc += __shfl_down_sync(0xFFFFFFFFu, acc, off);
    if (lane == 0) {
        out[node] = g_dis[node] * (acc + g_hw3[node]) + b3[0];
        g_cnt[node] = 0;        // restore invariant for next call
    }
}

// ================= launch =================
extern "C" void kernel_launch(void* const* d_in, const int* in_sizes, int n_in,
                              void* d_out, int out_size) {
    const float* x  = (const float*)d_in[0];
    const int*   ei = (const int*)d_in[1];
    const float* W1 = (const float*)d_in[2];
    const float* b1 = (const float*)d_in[3];
    const float* W2 = (const float*)d_in[4];
    const float* b2 = (const float*)d_in[5];
    const float* W3 = (const float*)d_in[6];
    const float* b3 = (const float*)d_in[7];
    float* out = (float*)d_out;

    const int TB = 256;
    k_fill<<<(NE / 4 + TB - 1) / TB, TB>>>(ei);

    // --- layer 1 (gemm1 also finalizes dis/padding/sentinel) ---
    k_gemm1<<<(NN + 127) / 128, 128>>>(x, W1);
    k_gather64<false><<<(NN + 7) / 8, TB>>>(b1, nullptr);

    // --- layer 2 (gather also computes hw3 = dis * (relu @ W3)) ---
    k_gemm2<<<(NN + 127) / 128, 128>>>(W2);
    k_gather64<true><<<(NN + 7) / 8, TB>>>(b2, W3);

    // --- layer 3 ---
    k_gather1<<<(NN + 7) / 8, TB>>>(out, b3);
}